// round 15
// baseline (speedup 1.0000x reference)
#include <cuda_runtime.h>
#include <cuda_bf16.h>
#include <cstdint>

// ---------------------------------------------------------------------------
// Round 15: dual-recurrence interleave. 32 batch-groups of M=16; each CTA
// owns gate-slice (N=128) of TWO groups (g0=2c, g1=2c+1) and alternates
// half-steps, so one recurrence's exchange latency hides under the other's
// compute. 288 threads = 8 compute warps + 1 exchange warp.
// Math unchanged: 3-pass bf16-split mma.sync, gate-interleaved B columns,
// in-register epilogue, B_hi register-resident, staged coalesced publish.
// ---------------------------------------------------------------------------

#define SEQ     512
#define BATCH   512
#define INPUT   128
#define HIDDEN  256
#define NGROUP  32
#define NSLICE  8
#define NCTA    128
#define NTHR    288
#define MR      16
#define NC      128
#define KTOT    384

// smem layout (bytes)
#define BPITCH  784
#define XPITCH  272
#define HPITCH  528
#define BLO_O   0            // 128*784 = 100352
#define XBASE   100352       // x: 2 recs x 2 bufs x 8704 (hi 4352 + lo 4352)
#define XBUFSZ  8704
#define XLOFF   4352
#define HBASE   135168       // h: 2 recs x 2 bufs x 16896 (hi 8448 + lo 8448)
#define HBUFSZ  16896
#define HLOFF   8448
#define HSTG    202752       // stage: 2 recs x 2560 (hi 1280 + lo 1280), pitch 80
#define HSTG_PITCH 80
#define HSTG_REC 2560
#define HSTG_LO 1280
#define SMEM_BYTES 207872

__device__ __align__(16) __nv_bfloat16 g_xhi[SEQ * BATCH * INPUT];
__device__ __align__(16) __nv_bfloat16 g_xlo[SEQ * BATCH * INPUT];
__device__ __align__(16) __nv_bfloat16 g_hh[2][NGROUP][MR][HIDDEN];
__device__ __align__(16) __nv_bfloat16 g_hl[2][NGROUP][MR][HIDDEN];
__device__ int g_flag[NGROUP][NSLICE][32];

// ---------------------------------------------------------------------------
__device__ __forceinline__ uint32_t smem_u32(const void* p) {
    uint32_t a;
    asm("{ .reg .u64 t; cvta.to.shared.u64 t, %1; cvt.u32.u64 %0, t; }"
        : "=r"(a) : "l"(p));
    return a;
}
__device__ __forceinline__ void ldsm4(uint32_t* r, uint32_t addr) {
    asm volatile("ldmatrix.sync.aligned.m8n8.x4.shared.b16 {%0,%1,%2,%3}, [%4];"
        : "=r"(r[0]), "=r"(r[1]), "=r"(r[2]), "=r"(r[3]) : "r"(addr));
}
__device__ __forceinline__ void ldsm2(uint32_t* r, uint32_t addr) {
    asm volatile("ldmatrix.sync.aligned.m8n8.x2.shared.b16 {%0,%1}, [%2];"
        : "=r"(r[0]), "=r"(r[1]) : "r"(addr));
}
__device__ __forceinline__ void mma_bf16(float* d, const uint32_t* a,
                                         const uint32_t* b) {
    asm volatile("mma.sync.aligned.m16n8k16.row.col.f32.bf16.bf16.f32 "
        "{%0,%1,%2,%3}, {%4,%5,%6,%7}, {%8,%9}, {%0,%1,%2,%3};"
        : "+f"(d[0]), "+f"(d[1]), "+f"(d[2]), "+f"(d[3])
        : "r"(a[0]), "r"(a[1]), "r"(a[2]), "r"(a[3]), "r"(b[0]), "r"(b[1]));
}
__device__ __forceinline__ void cpasync16(uint32_t dst, const void* src) {
    asm volatile("cp.async.cg.shared.global [%0], [%1], 16;"
        :: "r"(dst), "l"(src));
}
#define CP_COMMIT() asm volatile("cp.async.commit_group;" ::: "memory")
#define CP_WAIT0()  asm volatile("cp.async.wait_group 0;" ::: "memory")

#define BAR_SYNC(id, n)   asm volatile("bar.sync %0, %1;" :: "r"(id), "r"(n) : "memory")
#define BAR_ARRIVE(id, n) asm volatile("bar.arrive %0, %1;" :: "r"(id), "r"(n) : "memory")

__device__ __forceinline__ void st_release(int* p, int v) {
    asm volatile("st.release.gpu.global.b32 [%0], %1;" :: "l"(p), "r"(v) : "memory");
}
__device__ __forceinline__ int ld_acquire(const int* p) {
    int v;
    asm volatile("ld.acquire.gpu.global.u32 %0, [%1];" : "=r"(v) : "l"(p) : "memory");
    return v;
}

__device__ __forceinline__ float sigf(float v)  { return 1.0f / (1.0f + __expf(-v)); }
__device__ __forceinline__ float tanhx(float v) { return 2.0f / (1.0f + __expf(-2.0f * v)) - 1.0f; }
__device__ __forceinline__ uint32_t pk2(float a, float b) {
    __nv_bfloat162 t = __floats2bfloat162_rn(a, b);
    return *reinterpret_cast<uint32_t*>(&t);
}

// ---------------------------------------------------------------------------
__global__ void prep_x(const float* __restrict__ x) {
    const int N4 = SEQ * BATCH * INPUT / 4;
    for (int i = blockIdx.x * blockDim.x + threadIdx.x; i < N4;
         i += gridDim.x * blockDim.x) {
        float4 v = *reinterpret_cast<const float4*>(x + 4 * i);
        float hx = __bfloat162float(__float2bfloat16(v.x));
        float hy = __bfloat162float(__float2bfloat16(v.y));
        float hz = __bfloat162float(__float2bfloat16(v.z));
        float hw = __bfloat162float(__float2bfloat16(v.w));
        uint2 hi, lo;
        hi.x = pk2(v.x, v.y); hi.y = pk2(v.z, v.w);
        lo.x = pk2(v.x - hx, v.y - hy); lo.y = pk2(v.z - hz, v.w - hw);
        reinterpret_cast<uint2*>(g_xhi)[i] = hi;
        reinterpret_cast<uint2*>(g_xlo)[i] = lo;
    }
}

// ---------------------------------------------------------------------------
// Gate-interleaved column mapping: n = 16nq+8nt+2q+e -> gate(2nt+e), unit(4nq+q)
__device__ __forceinline__ int map_gcol(int n, int slice) {
    int nq = n >> 4, nt = (n >> 3) & 1, q = (n >> 1) & 3, e = n & 1;
    return (2 * nt + e) * HIDDEN + slice * 32 + (4 * nq + q);
}

// x-part GEMM (kt 0..7), M=16 per rec
__device__ __forceinline__ void gemm_x(float d[2][4], uint32_t bx, uint32_t bBL,
                                       const uint32_t bh[24][2][2]) {
    #pragma unroll
    for (int kt = 0; kt < 8; ++kt) {
        uint32_t ah[4], al[4], b0[2], b1[2];
        ldsm4(ah, bx + kt * 32);
        ldsm4(al, bx + XLOFF + kt * 32);
        ldsm2(b0, bBL + kt * 32);
        ldsm2(b1, bBL + 8 * BPITCH + kt * 32);
        mma_bf16(d[0], ah, bh[kt][0]); mma_bf16(d[1], ah, bh[kt][1]);
        mma_bf16(d[0], al, bh[kt][0]); mma_bf16(d[1], al, bh[kt][1]);
        mma_bf16(d[0], ah, b0);        mma_bf16(d[1], ah, b1);
    }
}
// h-part GEMM (kt 8..23)
__device__ __forceinline__ void gemm_h(float d[2][4], uint32_t bhm, uint32_t bBL,
                                       const uint32_t bh[24][2][2]) {
    #pragma unroll
    for (int kt = 8; kt < 24; ++kt) {
        uint32_t ah[4], al[4], b0[2], b1[2];
        uint32_t ko = (kt - 8) * 32;
        ldsm4(ah, bhm + ko);
        ldsm4(al, bhm + HLOFF + ko);
        ldsm2(b0, bBL + kt * 32);
        ldsm2(b1, bBL + 8 * BPITCH + kt * 32);
        mma_bf16(d[0], ah, bh[kt][0]); mma_bf16(d[1], ah, bh[kt][1]);
        mma_bf16(d[0], al, bh[kt][0]); mma_bf16(d[1], al, bh[kt][1]);
        mma_bf16(d[0], ah, b0);        mma_bf16(d[1], ah, b1);
    }
}

__global__ void __launch_bounds__(NTHR, 1)
lstm_mma(const float* __restrict__ W_ih, const float* __restrict__ W_hh,
         const float* __restrict__ b_ih, const float* __restrict__ b_hh,
         const float* __restrict__ W_out, const float* __restrict__ b_out,
         float* __restrict__ out) {
    extern __shared__ char smem[];
    const uint32_t sA = smem_u32(smem);

    const int tid  = threadIdx.x;
    const int wid  = tid >> 5;
    const int lane = tid & 31;
    const int c     = blockIdx.x >> 3;      // group pair index (0..15)
    const int slice = blockIdx.x & 7;
    const int g0 = 2 * c, g1 = 2 * c + 1;
    const bool is_x = (wid == 8);
    const int nq = wid;
    const int l15 = lane & 15;

    // ---- build B_lo (gate-interleaved) ----
    for (int i = tid; i < NC * KTOT; i += NTHR) {
        int n = i / KTOT, k = i - n * KTOT;
        int gcol = map_gcol(n, slice);
        float wv = (k < INPUT) ? W_ih[(size_t)gcol * INPUT + k]
                               : W_hh[(size_t)gcol * HIDDEN + (k - INPUT)];
        __nv_bfloat16 bhv = __float2bfloat16(wv);
        __nv_bfloat16 blv = __float2bfloat16(wv - __bfloat162float(bhv));
        *reinterpret_cast<__nv_bfloat16*>(smem + BLO_O + n * BPITCH + 2 * k) = blv;
    }
    // ---- B_hi -> compute-warp registers, 2 phases (alias x/h region) ----
    uint32_t bh[24][2][2];
    #pragma unroll
    for (int p = 0; p < 2; ++p) {
        __syncthreads();
        for (int i = tid; i < 64 * KTOT; i += NTHR) {
            int n = i / KTOT, k = i - n * KTOT;
            int gcol = map_gcol(p * 64 + n, slice);
            float wv = (k < INPUT) ? W_ih[(size_t)gcol * INPUT + k]
                                   : W_hh[(size_t)gcol * HIDDEN + (k - INPUT)];
            *reinterpret_cast<__nv_bfloat16*>(smem + XBASE + n * BPITCH + 2 * k) =
                __float2bfloat16(wv);
        }
        __syncthreads();
        if (!is_x && (nq >> 2) == p) {
            int nloc = 16 * (nq & 3);
            uint32_t base = sA + XBASE + (uint32_t)(nloc + (l15 & 7)) * BPITCH
                          + (uint32_t)((l15 >> 3) & 1) * 16;
            #pragma unroll
            for (int kt = 0; kt < 24; ++kt) {
                ldsm2(&bh[kt][0][0], base + kt * 32);
                ldsm2(&bh[kt][1][0], base + 8 * BPITCH + kt * 32);
            }
        }
    }
    __syncthreads();

    // ---- zero whole h region (buf0 of both recs must be 0 at s=0) ----
    for (int i = tid; i < (HSTG - HBASE) / 4; i += NTHR)
        reinterpret_cast<uint32_t*>(smem + HBASE)[i] = 0;

    // ---- stage x[0] for both recs into buf 0 ----
    #pragma unroll
    for (int rec = 0; rec < 2; ++rec) {
        int gg = g0 + rec;
        const __nv_bfloat16* xh_ = g_xhi + (size_t)(gg * MR) * INPUT;
        const __nv_bfloat16* xl_ = g_xlo + (size_t)(gg * MR) * INPUT;
        uint32_t xb = sA + XBASE + (uint32_t)(rec * 2) * XBUFSZ;
        for (int i = tid; i < MR * 16; i += NTHR) {
            int r = i >> 4, ch = i & 15;
            uint32_t dst = xb + r * XPITCH + ch * 16;
            cpasync16(dst, xh_ + r * INPUT + ch * 8);
            cpasync16(dst + XLOFF, xl_ + r * INPUT + ch * 8);
        }
    }
    CP_COMMIT();
    CP_WAIT0();
    __syncthreads();

    if (is_x) {
        // ======================= EXCHANGE WARP =======================
        for (int s = 0; s < SEQ; ++s) {
            const int tag = s & 1;
            #pragma unroll
            for (int rec = 0; rec < 2; ++rec) {
                int gg = g0 + rec;
                if (s > 0) {
                    if (lane < 8)
                        while (ld_acquire(&g_flag[gg][lane][0]) != tag) __nanosleep(16);
                    __syncwarp();
                    const __nv_bfloat16* hh = &g_hh[(s - 1) & 1][gg][0][0];
                    const __nv_bfloat16* hl = &g_hl[(s - 1) & 1][gg][0][0];
                    uint32_t hb = sA + HBASE + (uint32_t)(rec * 2 + (s & 1)) * HBUFSZ;
                    for (int i = lane; i < MR * 32; i += 32) {
                        int r = i >> 5, ch = i & 31;
                        uint32_t dst = hb + r * HPITCH + ch * 16;
                        cpasync16(dst, hh + r * HIDDEN + ch * 8);
                        cpasync16(dst + HLOFF, hl + r * HIDDEN + ch * 8);
                    }
                }
                if (s + 1 < SEQ) {
                    const __nv_bfloat16* xh_ =
                        g_xhi + ((size_t)(s + 1) * BATCH + gg * MR) * INPUT;
                    const __nv_bfloat16* xl_ =
                        g_xlo + ((size_t)(s + 1) * BATCH + gg * MR) * INPUT;
                    uint32_t xb = sA + XBASE
                                + (uint32_t)(rec * 2 + ((s + 1) & 1)) * XBUFSZ;
                    for (int i = lane; i < MR * 16; i += 32) {
                        int r = i >> 4, ch = i & 15;
                        uint32_t dst = xb + r * XPITCH + ch * 16;
                        cpasync16(dst, xh_ + r * INPUT + ch * 8);
                        cpasync16(dst + XLOFF, xl_ + r * INPUT + ch * 8);
                    }
                }
                CP_COMMIT();
                CP_WAIT0();
                BAR_ARRIVE(rec ? 3 : 1, NTHR);   // H0 / H1 staged
            }
            // publish acks
            BAR_SYNC(2, NTHR);                   // P0: rec0 copy-out done
            if (lane == 0) {
                __threadfence();
                st_release(&g_flag[g0][slice][0], tag ^ 1);
            }
            BAR_SYNC(6, NTHR);                   // P1: rec1 copy-out done
            if (lane == 0) {
                __threadfence();
                st_release(&g_flag[g1][slice][0], tag ^ 1);
            }
            __syncwarp();
        }
        // final: wait both groups' step-511 publishes (tag -> 0)
        if (lane < 8) {
            while (ld_acquire(&g_flag[g0][lane][0]) != 0) __nanosleep(16);
            while (ld_acquire(&g_flag[g1][lane][0]) != 0) __nanosleep(16);
        }
        __syncwarp();
    } else {
        // ======================= COMPUTE WARPS =======================
        const uint32_t baseBL = sA + BLO_O
            + (uint32_t)(16 * nq + (l15 & 7)) * BPITCH
            + (uint32_t)((l15 >> 3) & 1) * 16;
        const uint32_t aoffX = (uint32_t)l15 * XPITCH + (uint32_t)(lane >> 4) * 16;
        const uint32_t aoffH = (uint32_t)l15 * HPITCH + (uint32_t)(lane >> 4) * 16;

        const int q = lane & 3;
        const int unit_l = 4 * nq + q;
        const int gunit = slice * 32 + unit_l;
        float cb[2][2];
        #pragma unroll
        for (int nt = 0; nt < 2; ++nt)
            #pragma unroll
            for (int e = 0; e < 2; ++e) {
                int gcol = (2 * nt + e) * HIDDEN + gunit;
                cb[nt][e] = b_ih[gcol] + b_hh[gcol];
            }

        float cst[2][2] = {{0.f, 0.f}, {0.f, 0.f}};

        for (int s = 0; s < SEQ; ++s) {
            #pragma unroll
            for (int rec = 0; rec < 2; ++rec) {
                float d[2][4];
                #pragma unroll
                for (int nt = 0; nt < 2; ++nt) {
                    d[nt][0] = cb[nt][0]; d[nt][1] = cb[nt][1];
                    d[nt][2] = cb[nt][0]; d[nt][3] = cb[nt][1];
                }
                // x-part (buffer written at H-phase of s-1, visible via bar)
                uint32_t bx = sA + XBASE + (uint32_t)(rec * 2 + (s & 1)) * XBUFSZ
                            + aoffX;
                gemm_x(d, bx, baseBL, bh);

                BAR_SYNC(rec ? 3 : 1, NTHR);     // h(s-1) of this rec staged

                uint32_t bhm = sA + HBASE + (uint32_t)(rec * 2 + (s & 1)) * HBUFSZ
                             + aoffH;
                gemm_h(d, bhm, baseBL, bh);

                // in-register epilogue -> stage tile
                #pragma unroll
                for (int h2 = 0; h2 < 2; ++h2) {
                    float iv = d[0][2 * h2 + 0];
                    float fv = d[0][2 * h2 + 1];
                    float gv = d[1][2 * h2 + 0];
                    float ov = d[1][2 * h2 + 1];
                    cst[rec][h2] = sigf(fv) * cst[rec][h2] + sigf(iv) * tanhx(gv);
                    float hn = sigf(ov) * tanhx(cst[rec][h2]);
                    __nv_bfloat16 hb16 = __float2bfloat16(hn);
                    __nv_bfloat16 lb16 = __float2bfloat16(hn - __bfloat162float(hb16));
                    int r = 8 * h2 + (lane >> 2);
                    char* stg = smem + HSTG + rec * HSTG_REC;
                    *reinterpret_cast<__nv_bfloat16*>(
                        stg + r * HSTG_PITCH + 2 * unit_l) = hb16;
                    *reinterpret_cast<__nv_bfloat16*>(
                        stg + HSTG_LO + r * HSTG_PITCH + 2 * unit_l) = lb16;
                }
                BAR_SYNC(rec ? 5 : 4, 256);      // compute-only: stage done

                // coalesced copy-out: 128 threads x 16B
                if (tid < 128) {
                    int plane = tid >> 6;
                    int idx = tid & 63;
                    int row = idx >> 2, cpos = idx & 3;
                    uint4 v = *reinterpret_cast<const uint4*>(
                        smem + HSTG + rec * HSTG_REC + plane * HSTG_LO
                        + row * HSTG_PITCH + cpos * 16);
                    int gg = g0 + rec;
                    __nv_bfloat16* dst = plane
                        ? &g_hl[s & 1][gg][row][slice * 32 + cpos * 8]
                        : &g_hh[s & 1][gg][row][slice * 32 + cpos * 8];
                    __stcg(reinterpret_cast<uint4*>(dst), v);
                }
                BAR_ARRIVE(rec ? 6 : 2, NTHR);   // P0 / P1
            }
        }
    }

    __syncthreads();   // exchange warp verified all final publishes

    // ---- final projection (slice 0, compute warps): 32 rows (both groups) --
    if (slice == 0 && !is_x) {
        const float bo = b_out[0];
        for (int r4 = 0; r4 < 4; ++r4) {
            int idx = wid * 4 + r4;              // 0..31
            int gg = (idx < 16) ? g0 : g1;
            int r = idx & 15;
            int c0 = lane * 8;
            uint4 hv = __ldcg(reinterpret_cast<const uint4*>(&g_hh[1][gg][r][c0]));
            uint4 lv = __ldcg(reinterpret_cast<const uint4*>(&g_hl[1][gg][r][c0]));
            float acc = 0.0f;
            const uint32_t* hp = &hv.x;
            const uint32_t* lp = &lv.x;
            #pragma unroll
            for (int qq = 0; qq < 4; ++qq) {
                float2 h2 = __bfloat1622float2(*reinterpret_cast<const __nv_bfloat162*>(&hp[qq]));
                float2 l2 = __bfloat1622float2(*reinterpret_cast<const __nv_bfloat162*>(&lp[qq]));
                acc += (h2.x + l2.x) * W_out[c0 + 2 * qq]
                     + (h2.y + l2.y) * W_out[c0 + 2 * qq + 1];
            }
            #pragma unroll
            for (int off = 16; off > 0; off >>= 1)
                acc += __shfl_xor_sync(0xFFFFFFFFu, acc, off);
            if (lane == 0) out[gg * MR + r] = acc + bo;
        }
    }
}

// ---------------------------------------------------------------------------
extern "C" void kernel_launch(void* const* d_in, const int* in_sizes, int n_in,
                              void* d_out, int out_size) {
    const float* x     = (const float*)d_in[0];
    const float* W_ih  = (const float*)d_in[1];
    const float* W_hh  = (const float*)d_in[2];
    const float* b_ih  = (const float*)d_in[3];
    const float* b_hh  = (const float*)d_in[4];
    const float* W_out = (const float*)d_in[5];
    const float* b_out = (const float*)d_in[6];
    float* out = (float*)d_out;

    prep_x<<<2048, 256>>>(x);
    cudaFuncSetAttribute(lstm_mma,
                         cudaFuncAttributeMaxDynamicSharedMemorySize, SMEM_BYTES);
    lstm_mma<<<NCTA, NTHR, SMEM_BYTES>>>(W_ih, W_hh, b_ih, b_hh,
                                         W_out, b_out, out);
}

// round 16
// speedup vs baseline: 1.1248x; 1.1248x over previous
#include <cuda_runtime.h>
#include <cuda_bf16.h>
#include <cstdint>

// ---------------------------------------------------------------------------
// Round 16 = Round 14 + software-pipelined GEMM loops: fragments for kt+1
// (4x ldsm4 A + 2x ldsm2 B_lo) are loaded while kt's 12 MMAs execute
// (explicit double-buffered register fragments). Everything else identical
// to R14: 3-pass bf16-split mma.sync, gate-interleaved B, in-register
// epilogue, staged coalesced publish, per-producer flags, split h copy.
// Geometry: 16 batch-groups (M=32) x 8 slices (N=128) = 128 CTAs, 1/SM,
// 288 threads = 8 compute warps + 1 exchange warp.
// ---------------------------------------------------------------------------

#define SEQ     512
#define BATCH   512
#define INPUT   128
#define HIDDEN  256
#define NGROUP  16
#define NSLICE  8
#define NCTA    128
#define NTHR    288
#define MR      32
#define NC      128
#define KTOT    384

// smem layout (bytes)
#define BPITCH  784
#define XPITCH  272
#define HPITCH  528
#define BLO_O   0            // 128*784 = 100352
#define XB0     100352       // x: 2 bufs x (hi 8704 + lo 8704)
#define XBSTRIDE 17408
#define XLOFF   8704
#define HB0     135168       // h: 2 bufs x (hi 16896 + lo 16896)
#define HBSTRIDE 33792
#define HLOFF   16896
#define HSTG    202752       // h staging: 2 planes x 32 rows x 80B
#define HSTG_PITCH 80
#define HSTG_LO 2560
#define SMEM_BYTES 207872

__device__ __align__(16) __nv_bfloat16 g_xhi[SEQ * BATCH * INPUT];
__device__ __align__(16) __nv_bfloat16 g_xlo[SEQ * BATCH * INPUT];
__device__ __align__(16) __nv_bfloat16 g_hh[2][NGROUP][MR][HIDDEN];
__device__ __align__(16) __nv_bfloat16 g_hl[2][NGROUP][MR][HIDDEN];
__device__ int g_flag[NGROUP][NSLICE][32];

// ---------------------------------------------------------------------------
__device__ __forceinline__ uint32_t smem_u32(const void* p) {
    uint32_t a;
    asm("{ .reg .u64 t; cvta.to.shared.u64 t, %1; cvt.u32.u64 %0, t; }"
        : "=r"(a) : "l"(p));
    return a;
}
__device__ __forceinline__ void ldsm4(uint32_t* r, uint32_t addr) {
    asm volatile("ldmatrix.sync.aligned.m8n8.x4.shared.b16 {%0,%1,%2,%3}, [%4];"
        : "=r"(r[0]), "=r"(r[1]), "=r"(r[2]), "=r"(r[3]) : "r"(addr));
}
__device__ __forceinline__ void ldsm2(uint32_t* r, uint32_t addr) {
    asm volatile("ldmatrix.sync.aligned.m8n8.x2.shared.b16 {%0,%1}, [%2];"
        : "=r"(r[0]), "=r"(r[1]) : "r"(addr));
}
__device__ __forceinline__ void mma_bf16(float* d, const uint32_t* a,
                                         const uint32_t* b) {
    asm volatile("mma.sync.aligned.m16n8k16.row.col.f32.bf16.bf16.f32 "
        "{%0,%1,%2,%3}, {%4,%5,%6,%7}, {%8,%9}, {%0,%1,%2,%3};"
        : "+f"(d[0]), "+f"(d[1]), "+f"(d[2]), "+f"(d[3])
        : "r"(a[0]), "r"(a[1]), "r"(a[2]), "r"(a[3]), "r"(b[0]), "r"(b[1]));
}
__device__ __forceinline__ void cpasync16(uint32_t dst, const void* src) {
    asm volatile("cp.async.cg.shared.global [%0], [%1], 16;"
        :: "r"(dst), "l"(src));
}
#define CP_COMMIT() asm volatile("cp.async.commit_group;" ::: "memory")
#define CP_WAIT0()  asm volatile("cp.async.wait_group 0;" ::: "memory")
#define CP_WAIT2()  asm volatile("cp.async.wait_group 2;" ::: "memory")

#define BAR_SYNC(id, n)   asm volatile("bar.sync %0, %1;" :: "r"(id), "r"(n) : "memory")
#define BAR_ARRIVE(id, n) asm volatile("bar.arrive %0, %1;" :: "r"(id), "r"(n) : "memory")

__device__ __forceinline__ void st_release(int* p, int v) {
    asm volatile("st.release.gpu.global.b32 [%0], %1;" :: "l"(p), "r"(v) : "memory");
}
__device__ __forceinline__ int ld_acquire(const int* p) {
    int v;
    asm volatile("ld.acquire.gpu.global.u32 %0, [%1];" : "=r"(v) : "l"(p) : "memory");
    return v;
}

__device__ __forceinline__ float sigf(float v)  { return 1.0f / (1.0f + __expf(-v)); }
__device__ __forceinline__ float tanhx(float v) { return 2.0f / (1.0f + __expf(-2.0f * v)) - 1.0f; }
__device__ __forceinline__ uint32_t pk2(float a, float b) {
    __nv_bfloat162 t = __floats2bfloat162_rn(a, b);
    return *reinterpret_cast<uint32_t*>(&t);
}

// Fragment set for one kt iteration (pipelined).
struct Frag {
    uint32_t ah0[4], ah1[4], al0[4], al1[4], bl0[2], bl1[2];
};
// Load x-loop fragments for kt.
__device__ __forceinline__ void load_fx(Frag& f, uint32_t bx, uint32_t bBL, int kt) {
    ldsm4(f.ah0, bx + kt * 32);
    ldsm4(f.ah1, bx + 16 * XPITCH + kt * 32);
    ldsm4(f.al0, bx + XLOFF + kt * 32);
    ldsm4(f.al1, bx + XLOFF + 16 * XPITCH + kt * 32);
    ldsm2(f.bl0, bBL + kt * 32);
    ldsm2(f.bl1, bBL + 8 * BPITCH + kt * 32);
}
// Load h-loop fragments for kt (kt in 8..23).
__device__ __forceinline__ void load_fh(Frag& f, uint32_t bhm, uint32_t bBL, int kt) {
    uint32_t ko = (kt - 8) * 32;
    ldsm4(f.ah0, bhm + ko);
    ldsm4(f.ah1, bhm + 16 * HPITCH + ko);
    ldsm4(f.al0, bhm + HLOFF + ko);
    ldsm4(f.al1, bhm + HLOFF + 16 * HPITCH + ko);
    ldsm2(f.bl0, bBL + kt * 32);
    ldsm2(f.bl1, bBL + 8 * BPITCH + kt * 32);
}
// 12 MMAs (3 passes x 2m x 2n) for one kt on fragment f.
__device__ __forceinline__ void mma_kt(float d[2][2][4], const Frag& f,
                                       const uint32_t bhk[2][2]) {
    mma_bf16(d[0][0], f.ah0, bhk[0]); mma_bf16(d[0][1], f.ah0, bhk[1]);
    mma_bf16(d[1][0], f.ah1, bhk[0]); mma_bf16(d[1][1], f.ah1, bhk[1]);
    mma_bf16(d[0][0], f.al0, bhk[0]); mma_bf16(d[0][1], f.al0, bhk[1]);
    mma_bf16(d[1][0], f.al1, bhk[0]); mma_bf16(d[1][1], f.al1, bhk[1]);
    mma_bf16(d[0][0], f.ah0, f.bl0);  mma_bf16(d[0][1], f.ah0, f.bl1);
    mma_bf16(d[1][0], f.ah1, f.bl0);  mma_bf16(d[1][1], f.ah1, f.bl1);
}

// ---------------------------------------------------------------------------
__global__ void prep_x(const float* __restrict__ x) {
    const int N4 = SEQ * BATCH * INPUT / 4;
    for (int i = blockIdx.x * blockDim.x + threadIdx.x; i < N4;
         i += gridDim.x * blockDim.x) {
        float4 v = *reinterpret_cast<const float4*>(x + 4 * i);
        float hx = __bfloat162float(__float2bfloat16(v.x));
        float hy = __bfloat162float(__float2bfloat16(v.y));
        float hz = __bfloat162float(__float2bfloat16(v.z));
        float hw = __bfloat162float(__float2bfloat16(v.w));
        uint2 hi, lo;
        hi.x = pk2(v.x, v.y); hi.y = pk2(v.z, v.w);
        lo.x = pk2(v.x - hx, v.y - hy); lo.y = pk2(v.z - hz, v.w - hw);
        reinterpret_cast<uint2*>(g_xhi)[i] = hi;
        reinterpret_cast<uint2*>(g_xlo)[i] = lo;
    }
}

// ---------------------------------------------------------------------------
// Gate-interleaved column mapping: n = 16nq+8nt+2q+e -> gate(2nt+e), unit(4nq+q)
__device__ __forceinline__ int map_gcol(int n, int slice) {
    int nq = n >> 4, nt = (n >> 3) & 1, q = (n >> 1) & 3, e = n & 1;
    return (2 * nt + e) * HIDDEN + slice * 32 + (4 * nq + q);
}

__global__ void __launch_bounds__(NTHR, 1)
lstm_mma(const float* __restrict__ W_ih, const float* __restrict__ W_hh,
         const float* __restrict__ b_ih, const float* __restrict__ b_hh,
         const float* __restrict__ W_out, const float* __restrict__ b_out,
         float* __restrict__ out) {
    extern __shared__ char smem[];
    const uint32_t sA = smem_u32(smem);

    const int tid  = threadIdx.x;
    const int wid  = tid >> 5;
    const int lane = tid & 31;
    const int g     = blockIdx.x >> 3;
    const int slice = blockIdx.x & 7;
    const bool is_x = (wid == 8);
    const int nq = wid;
    const int l15 = lane & 15;

    // ---- build B_lo (gate-interleaved) ----
    for (int i = tid; i < NC * KTOT; i += NTHR) {
        int n = i / KTOT, k = i - n * KTOT;
        int gcol = map_gcol(n, slice);
        float wv = (k < INPUT) ? W_ih[(size_t)gcol * INPUT + k]
                               : W_hh[(size_t)gcol * HIDDEN + (k - INPUT)];
        __nv_bfloat16 bhv = __float2bfloat16(wv);
        __nv_bfloat16 blv = __float2bfloat16(wv - __bfloat162float(bhv));
        *reinterpret_cast<__nv_bfloat16*>(smem + BLO_O + n * BPITCH + 2 * k) = blv;
    }
    // ---- B_hi -> compute-warp registers, 2 phases (alias x/h region) ----
    uint32_t bh[24][2][2];
    #pragma unroll
    for (int p = 0; p < 2; ++p) {
        __syncthreads();
        for (int i = tid; i < 64 * KTOT; i += NTHR) {
            int n = i / KTOT, k = i - n * KTOT;
            int gcol = map_gcol(p * 64 + n, slice);
            float wv = (k < INPUT) ? W_ih[(size_t)gcol * INPUT + k]
                                   : W_hh[(size_t)gcol * HIDDEN + (k - INPUT)];
            *reinterpret_cast<__nv_bfloat16*>(smem + XB0 + n * BPITCH + 2 * k) =
                __float2bfloat16(wv);
        }
        __syncthreads();
        if (!is_x && (nq >> 2) == p) {
            int nloc = 16 * (nq & 3);
            uint32_t base = sA + XB0 + (uint32_t)(nloc + (l15 & 7)) * BPITCH
                          + (uint32_t)((l15 >> 3) & 1) * 16;
            #pragma unroll
            for (int kt = 0; kt < 24; ++kt) {
                ldsm2(&bh[kt][0][0], base + kt * 32);
                ldsm2(&bh[kt][1][0], base + 8 * BPITCH + kt * 32);
            }
        }
    }
    __syncthreads();

    // ---- zero h buffer 0 (h = 0 at step 0) ----
    for (int i = tid; i < HBSTRIDE / 4; i += NTHR)
        reinterpret_cast<uint32_t*>(smem + HB0)[i] = 0;

    // ---- stage x[0] into x-buffer 0 (all threads) ----
    {
        const __nv_bfloat16* xh_ = g_xhi + (size_t)(g * MR) * INPUT;
        const __nv_bfloat16* xl_ = g_xlo + (size_t)(g * MR) * INPUT;
        for (int i = tid; i < MR * 16; i += NTHR) {
            int r = i >> 4, ch = i & 15;
            uint32_t dst = sA + XB0 + r * XPITCH + ch * 16;
            cpasync16(dst, xh_ + r * INPUT + ch * 8);
            cpasync16(dst + XLOFF, xl_ + r * INPUT + ch * 8);
        }
        CP_COMMIT();
        CP_WAIT0();
    }
    __syncthreads();

    if (is_x) {
        // =================== EXCHANGE WARP ===================
        for (int s = 0; s < SEQ; ++s) {
            const int tag = s & 1;
            const __nv_bfloat16* hh = &g_hh[(s - 1) & 1][g][0][0];
            const __nv_bfloat16* hl = &g_hl[(s - 1) & 1][g][0][0];
            uint32_t hb = sA + HB0 + (uint32_t)(s & 1) * HBSTRIDE;

            if (s > 0) {   // phase A: producers 0..3 (units 0..127)
                if (lane < 4)
                    while (ld_acquire(&g_flag[g][lane][0]) != tag) __nanosleep(16);
                __syncwarp();
                for (int i = lane; i < MR * 16; i += 32) {
                    int r = i >> 4, ch = i & 15;
                    uint32_t dst = hb + r * HPITCH + ch * 16;
                    cpasync16(dst, hh + r * HIDDEN + ch * 8);
                    cpasync16(dst + HLOFF, hl + r * HIDDEN + ch * 8);
                }
            }
            CP_COMMIT();     // group h1

            if (s > 0) {   // phase B: producers 4..7 (units 128..255)
                if (lane < 4)
                    while (ld_acquire(&g_flag[g][4 + lane][0]) != tag) __nanosleep(16);
                __syncwarp();
                for (int i = lane; i < MR * 16; i += 32) {
                    int r = i >> 4, ch = 16 + (i & 15);
                    uint32_t dst = hb + r * HPITCH + ch * 16;
                    cpasync16(dst, hh + r * HIDDEN + ch * 8);
                    cpasync16(dst + HLOFF, hl + r * HIDDEN + ch * 8);
                }
            }
            CP_COMMIT();     // group h2

            if (s + 1 < SEQ) {   // x(s+1) prefetch
                const __nv_bfloat16* xh_ = g_xhi + ((size_t)(s + 1) * BATCH + g * MR) * INPUT;
                const __nv_bfloat16* xl_ = g_xlo + ((size_t)(s + 1) * BATCH + g * MR) * INPUT;
                uint32_t xb = sA + XB0 + (uint32_t)((s + 1) & 1) * XBSTRIDE;
                for (int i = lane; i < MR * 16; i += 32) {
                    int r = i >> 4, ch = i & 15;
                    uint32_t dst = xb + r * XPITCH + ch * 16;
                    cpasync16(dst, xh_ + r * INPUT + ch * 8);
                    cpasync16(dst + XLOFF, xl_ + r * INPUT + ch * 8);
                }
            }
            CP_COMMIT();     // group x

            CP_WAIT2();                  // h1 landed
            BAR_ARRIVE(3, NTHR);
            CP_WAIT0();                  // h2 + x landed
            BAR_ARRIVE(1, NTHR);
            BAR_SYNC(2, NTHR);           // compute epilogue + copy-out done
            if (lane == 0) {
                __threadfence();
                st_release(&g_flag[g][slice][0], tag ^ 1);
            }
            __syncwarp();
        }
        if (lane < 8)
            while (ld_acquire(&g_flag[g][lane][0]) != 0) __nanosleep(16);
        __syncwarp();
    } else {
        // =================== COMPUTE WARPS ===================
        const uint32_t baseX  = sA + XB0 + (uint32_t)l15 * XPITCH
                              + (uint32_t)(lane >> 4) * 16;
        const uint32_t baseH  = sA + HB0 + (uint32_t)l15 * HPITCH
                              + (uint32_t)(lane >> 4) * 16;
        const uint32_t baseBL = sA + BLO_O + (uint32_t)(16 * nq + (l15 & 7)) * BPITCH
                              + (uint32_t)((l15 >> 3) & 1) * 16;

        const int q = lane & 3;
        const int unit_l = 4 * nq + q;
        const int gunit = slice * 32 + unit_l;
        float cb[2][2];
        #pragma unroll
        for (int nt = 0; nt < 2; ++nt)
            #pragma unroll
            for (int e = 0; e < 2; ++e) {
                int gcol = (2 * nt + e) * HIDDEN + gunit;
                cb[nt][e] = b_ih[gcol] + b_hh[gcol];
            }

        float cst[4] = {0.f, 0.f, 0.f, 0.f};

        for (int s = 0; s < SEQ; ++s) {
            float d[2][2][4];
            #pragma unroll
            for (int mt = 0; mt < 2; ++mt)
                #pragma unroll
                for (int nt = 0; nt < 2; ++nt) {
                    d[mt][nt][0] = cb[nt][0]; d[mt][nt][1] = cb[nt][1];
                    d[mt][nt][2] = cb[nt][0]; d[mt][nt][3] = cb[nt][1];
                }

            // ---- x-part MMAs (kt 0..7), software-pipelined ----
            {
                uint32_t bx = baseX + (uint32_t)(s & 1) * XBSTRIDE;
                Frag f[2];
                load_fx(f[0], bx, baseBL, 0);
                #pragma unroll
                for (int kt = 0; kt < 8; ++kt) {
                    if (kt < 7) load_fx(f[(kt + 1) & 1], bx, baseBL, kt + 1);
                    mma_kt(d, f[kt & 1], bh[kt]);
                }
            }

            uint32_t bhm = baseH + (uint32_t)(s & 1) * HBSTRIDE;

            BAR_SYNC(3, NTHR);   // first half of h(s-1) staged

            // ---- h-part MMAs (kt 8..15), pipelined ----
            {
                Frag f[2];
                load_fh(f[0], bhm, baseBL, 8);
                #pragma unroll
                for (int kt = 8; kt < 16; ++kt) {
                    if (kt < 15) load_fh(f[(kt + 1) & 1], bhm, baseBL, kt + 1);
                    mma_kt(d, f[kt & 1], bh[kt]);
                }
            }

            BAR_SYNC(1, NTHR);   // second half staged (+ x(s+1) ready)

            // ---- h-part MMAs (kt 16..23), pipelined ----
            {
                Frag f[2];
                load_fh(f[0], bhm, baseBL, 16);
                #pragma unroll
                for (int kt = 16; kt < 24; ++kt) {
                    if (kt < 23) load_fh(f[(kt + 1) & 1], bhm, baseBL, kt + 1);
                    mma_kt(d, f[kt & 1], bh[kt]);
                }
            }

            // ---- in-register epilogue -> smem stage (bf16 hi/lo) ----
            #pragma unroll
            for (int mt = 0; mt < 2; ++mt)
                #pragma unroll
                for (int h2 = 0; h2 < 2; ++h2) {
                    float iv = d[mt][0][2 * h2 + 0];
                    float fv = d[mt][0][2 * h2 + 1];
                    float gv = d[mt][1][2 * h2 + 0];
                    float ov = d[mt][1][2 * h2 + 1];
                    int ci = 2 * mt + h2;
                    cst[ci] = sigf(fv) * cst[ci] + sigf(iv) * tanhx(gv);
                    float hn = sigf(ov) * tanhx(cst[ci]);
                    __nv_bfloat16 hb16 = __float2bfloat16(hn);
                    __nv_bfloat16 lb16 = __float2bfloat16(hn - __bfloat162float(hb16));
                    int r = 16 * mt + 8 * h2 + (lane >> 2);
                    *reinterpret_cast<__nv_bfloat16*>(
                        smem + HSTG + r * HSTG_PITCH + 2 * unit_l) = hb16;
                    *reinterpret_cast<__nv_bfloat16*>(
                        smem + HSTG + HSTG_LO + r * HSTG_PITCH + 2 * unit_l) = lb16;
                }

            BAR_SYNC(4, 256);    // compute-only: stage complete

            // ---- coalesced copy-out: 256 threads x one 16B chunk ----
            {
                int plane = tid >> 7;
                int idx = tid & 127;
                int row = idx >> 2;
                int cpos = idx & 3;
                uint4 v = *reinterpret_cast<const uint4*>(
                    smem + HSTG + plane * HSTG_LO + row * HSTG_PITCH + cpos * 16);
                __nv_bfloat16* dst = plane
                    ? &g_hl[s & 1][g][row][slice * 32 + cpos * 8]
                    : &g_hh[s & 1][g][row][slice * 32 + cpos * 8];
                __stcg(reinterpret_cast<uint4*>(dst), v);
            }

            BAR_ARRIVE(2, NTHR);   // exchange warp publishes flag
        }
    }

    __syncthreads();

    // ---- final projection (slice 0, compute warps) ----
    if (slice == 0 && !is_x) {
        const int buf = (SEQ - 1) & 1;
        const float bo = b_out[0];
        for (int r4 = 0; r4 < 4; ++r4) {
            int r = wid * 4 + r4;
            int c0 = lane * 8;
            uint4 hv = __ldcg(reinterpret_cast<const uint4*>(&g_hh[buf][g][r][c0]));
            uint4 lv = __ldcg(reinterpret_cast<const uint4*>(&g_hl[buf][g][r][c0]));
            float acc = 0.0f;
            const uint32_t* hp = &hv.x;
            const uint32_t* lp = &lv.x;
            #pragma unroll
            for (int qq = 0; qq < 4; ++qq) {
                float2 h2 = __bfloat1622float2(*reinterpret_cast<const __nv_bfloat162*>(&hp[qq]));
                float2 l2 = __bfloat1622float2(*reinterpret_cast<const __nv_bfloat162*>(&lp[qq]));
                acc += (h2.x + l2.x) * W_out[c0 + 2 * qq]
                     + (h2.y + l2.y) * W_out[c0 + 2 * qq + 1];
            }
            #pragma unroll
            for (int off = 16; off > 0; off >>= 1)
                acc += __shfl_xor_sync(0xFFFFFFFFu, acc, off);
            if (lane == 0) out[g * MR + r] = acc + bo;
        }
    }
}

// ---------------------------------------------------------------------------
extern "C" void kernel_launch(void* const* d_in, const int* in_sizes, int n_in,
                              void* d_out, int out_size) {
    const float* x     = (const float*)d_in[0];
    const float* W_ih  = (const float*)d_in[1];
    const float* W_hh  = (const float*)d_in[2];
    const float* b_ih  = (const float*)d_in[3];
    const float* b_hh  = (const float*)d_in[4];
    const float* W_out = (const float*)d_in[5];
    const float* b_out = (const float*)d_in[6];
    float* out = (float*)d_out;

    prep_x<<<2048, 256>>>(x);
    cudaFuncSetAttribute(lstm_mma,
                         cudaFuncAttributeMaxDynamicSharedMemorySize, SMEM_BYTES);
    lstm_mma<<<NCTA, NTHR, SMEM_BYTES>>>(W_ih, W_hh, b_ih, b_hh,
                                         W_out, b_out, out);
}